// round 1
// baseline (speedup 1.0000x reference)
#include <cuda_runtime.h>
#include <math_constants.h>

#define NQ   4096
#define NK   4096
#define FDIM 256
#define RADIUS2 9.0f
#define MAXN 128   // per-warp neighbor list capacity (expected ~14, Poisson tail safe)

// Scratch (no allocation allowed in kernel_launch)
__device__ float g_q[NQ * FDIM];
__device__ float g_k[NK * FDIM];
__device__ float g_v[NK * FDIM];
__device__ float g_att[NQ * FDIM];

// ---------------------------------------------------------------------------
// C[M,256] = A[M,256] @ W[256,256]^T + b   (W row-major [out,in])
// 64x64 tile, BK=16, 256 threads, 4x4 per thread.
// ---------------------------------------------------------------------------
__global__ void gemm_bias_kernel(const float* __restrict__ A,
                                 const float* __restrict__ W,
                                 const float* __restrict__ b,
                                 float* __restrict__ C)
{
    __shared__ float As[16][65];
    __shared__ float Ws[16][65];

    const int tid = threadIdx.x;
    const int m0 = blockIdx.x * 64;
    const int n0 = blockIdx.y * 64;

    const int row = tid >> 2;        // 0..63
    const int kc  = (tid & 3) * 4;   // 0,4,8,12
    const int ty  = tid >> 4;        // 0..15
    const int tx  = tid & 15;        // 0..15

    float acc[4][4] = {};

    for (int kt = 0; kt < 256; kt += 16) {
        float4 av = *(const float4*)(A + (m0 + row) * 256 + kt + kc);
        float4 wv = *(const float4*)(W + (n0 + row) * 256 + kt + kc);
        As[kc + 0][row] = av.x; As[kc + 1][row] = av.y;
        As[kc + 2][row] = av.z; As[kc + 3][row] = av.w;
        Ws[kc + 0][row] = wv.x; Ws[kc + 1][row] = wv.y;
        Ws[kc + 2][row] = wv.z; Ws[kc + 3][row] = wv.w;
        __syncthreads();

        #pragma unroll
        for (int k = 0; k < 16; k++) {
            float a[4], w[4];
            #pragma unroll
            for (int i = 0; i < 4; i++) { a[i] = As[k][ty * 4 + i]; }
            #pragma unroll
            for (int j = 0; j < 4; j++) { w[j] = Ws[k][tx * 4 + j]; }
            #pragma unroll
            for (int i = 0; i < 4; i++)
                #pragma unroll
                for (int j = 0; j < 4; j++)
                    acc[i][j] = fmaf(a[i], w[j], acc[i][j]);
        }
        __syncthreads();
    }

    #pragma unroll
    for (int i = 0; i < 4; i++) {
        #pragma unroll
        for (int j = 0; j < 4; j++) {
            int n = n0 + tx * 4 + j;
            C[(m0 + ty * 4 + i) * 256 + n] = acc[i][j] + b[n];
        }
    }
}

// ---------------------------------------------------------------------------
// Sparse masked attention. One CTA per query. 256 threads:
//   warp = head (8 heads), lane = head dim (32).
// Phase 1: each warp scans 512 keys, ballot-compacts passing indices
//          (deterministic, ascending order).
// Phase 2: online softmax over the merged per-warp lists, processed in
//          fixed warp order -> deterministic fp reduction order.
// ---------------------------------------------------------------------------
__global__ void attn_kernel(const float* __restrict__ cq,   // [NQ,3]
                            const float* __restrict__ ck,   // [NK,3]
                            float* __restrict__ out)        // [NQ,256]
{
    const int qi   = blockIdx.x;
    const int tid  = threadIdx.x;
    const int warp = tid >> 5;
    const int lane = tid & 31;

    __shared__ int nbr[8][MAXN];
    __shared__ int cnt[8];

    const float qx = cq[3 * qi + 0];
    const float qy = cq[3 * qi + 1];
    const float qz = cq[3 * qi + 2];

    // Phase 1: neighbor compaction
    int c = 0;
    const int base0 = warp * 512;
    for (int base = base0; base < base0 + 512; base += 32) {
        int j = base + lane;
        float dx = qx - ck[3 * j + 0];
        float dy = qy - ck[3 * j + 1];
        float dz = qz - ck[3 * j + 2];
        float d2 = dx * dx + dy * dy + dz * dz;
        bool pass = (d2 <= RADIUS2);
        unsigned mk = __ballot_sync(0xffffffffu, pass);
        if (pass) {
            int pos = c + __popc(mk & ((1u << lane) - 1u));
            if (pos < MAXN) nbr[warp][pos] = j;
        }
        c += __popc(mk);
    }
    if (lane == 0) cnt[warp] = (c < MAXN) ? c : MAXN;
    __syncthreads();

    // Phase 2: online softmax + AV accumulation
    const float qv = g_q[qi * 256 + tid];
    float m = -CUDART_INF_F;
    float l = 0.0f;
    float acc = 0.0f;

    for (int w = 0; w < 8; w++) {
        const int n = cnt[w];
        for (int i = 0; i < n; i++) {
            const int j = nbr[w][i];
            float p = qv * g_k[j * 256 + tid];
            #pragma unroll
            for (int off = 16; off; off >>= 1)
                p += __shfl_xor_sync(0xffffffffu, p, off);
            float s  = p * 0.17677669529663687f;   // 1/sqrt(32)
            float mn = fmaxf(m, s);
            float cr = __expf(m - mn);             // exp(-inf)=0 handles first iter
            float e  = __expf(s - mn);
            l   = l * cr + e;
            acc = acc * cr + e * g_v[j * 256 + tid];
            m   = mn;
        }
    }
    out[qi * 256 + tid] = acc / l;
}

// ---------------------------------------------------------------------------
extern "C" void kernel_launch(void* const* d_in, const int* in_sizes, int n_in,
                              void* d_out, int out_size)
{
    const float* cur_f  = (const float*)d_in[0];
    const float* hist_f = (const float*)d_in[1];
    const float* cur_c  = (const float*)d_in[2];
    const float* hist_c = (const float*)d_in[3];
    const float* Wq = (const float*)d_in[4];
    const float* bq = (const float*)d_in[5];
    const float* Wk = (const float*)d_in[6];
    const float* bk = (const float*)d_in[7];
    const float* Wv = (const float*)d_in[8];
    const float* bv = (const float*)d_in[9];
    const float* Wo = (const float*)d_in[10];
    const float* bo = (const float*)d_in[11];
    float* out = (float*)d_out;

    float *pq, *pk, *pv, *patt;
    cudaGetSymbolAddress((void**)&pq,   g_q);
    cudaGetSymbolAddress((void**)&pk,   g_k);
    cudaGetSymbolAddress((void**)&pv,   g_v);
    cudaGetSymbolAddress((void**)&patt, g_att);

    dim3 gg(NQ / 64, FDIM / 64);
    dim3 gb(256);

    gemm_bias_kernel<<<gg, gb>>>(cur_f,  Wq, bq, pq);
    gemm_bias_kernel<<<gg, gb>>>(hist_f, Wk, bk, pk);
    gemm_bias_kernel<<<gg, gb>>>(hist_f, Wv, bv, pv);

    attn_kernel<<<NQ, 256>>>(cur_c, hist_c, patt);

    gemm_bias_kernel<<<gg, gb>>>(patt, Wo, bo, out);
}